// round 16
// baseline (speedup 1.0000x reference)
#include <cuda_runtime.h>
#include <cuda_fp16.h>
#include <stdint.h>

#define B_    64
#define H_    6
#define N_    512
#define D_    32
#define NIDX  43
#define LOG2E 1.4426950408889634f

// smem: K image 32KB | V f16 row-major [512][40] (80B rows) | wts | bias
#define SK_OFF   0
#define SV_OFF   32768
#define VROW_B   80
#define WT_OFF   (SV_OFF + N_*VROW_B)      // 73728
#define SB_OFF   (WT_OFF + 2048)           // 75776
#define SMEM_SZ  (SB_OFF + 192)            // 75968 -> 2 CTAs/SM

// ---------------- helpers ----------------
__device__ __forceinline__ uint32_t pkf16(float x0, float x1) {
    uint32_t r; asm("cvt.rn.f16x2.f32 %0, %1, %2;" : "=r"(r) : "f"(x1), "f"(x0)); return r;
}
__device__ __forceinline__ uint32_t hadd2(uint32_t a, uint32_t b) {
    uint32_t r; asm("add.rn.f16x2 %0, %1, %2;" : "=r"(r) : "r"(a), "r"(b)); return r;
}
__device__ __forceinline__ uint32_t hex2(uint32_t a) {
    uint32_t r; asm("ex2.approx.f16x2 %0, %1;" : "=r"(r) : "r"(a)); return r;
}
__device__ __forceinline__ void mma_f16(float c[4], const uint32_t a[4], uint32_t b0, uint32_t b1) {
    asm volatile(
        "mma.sync.aligned.m16n8k16.row.col.f32.f16.f16.f32 "
        "{%0,%1,%2,%3}, {%4,%5,%6,%7}, {%8,%9}, {%0,%1,%2,%3};\n"
        : "+f"(c[0]), "+f"(c[1]), "+f"(c[2]), "+f"(c[3])
        : "r"(a[0]), "r"(a[1]), "r"(a[2]), "r"(a[3]), "r"(b0), "r"(b1));
}
__device__ __forceinline__ void mma_f16_zc(float d[4], const uint32_t a[4], uint32_t b0, uint32_t b1) {
    asm volatile(
        "mma.sync.aligned.m16n8k16.row.col.f32.f16.f16.f32 "
        "{%0,%1,%2,%3}, {%4,%5,%6,%7}, {%8,%9}, {%10,%11,%12,%13};\n"
        : "=f"(d[0]), "=f"(d[1]), "=f"(d[2]), "=f"(d[3])
        : "r"(a[0]), "r"(a[1]), "r"(a[2]), "r"(a[3]), "r"(b0), "r"(b1),
          "f"(0.f), "f"(0.f), "f"(0.f), "f"(0.f));
}
#define LDSM4T(b0, b1, b2, b3, addr) \
    asm volatile("ldmatrix.sync.aligned.m8n8.x4.trans.shared.b16 {%0,%1,%2,%3}, [%4];" \
        : "=r"(b0), "=r"(b1), "=r"(b2), "=r"(b3) : "r"(addr))

__device__ __forceinline__ void ln_relu12(const float* x, const float* g, const float* b, float* y) {
    float mu = 0.f;
    #pragma unroll
    for (int j = 0; j < 12; j++) mu += x[j];
    mu *= (1.f / 12.f);
    float var = 0.f;
    #pragma unroll
    for (int j = 0; j < 12; j++) { float d = x[j] - mu; var += d * d; }
    var *= (1.f / 12.f);
    float inv = rsqrtf(var + 1e-5f);
    #pragma unroll
    for (int j = 0; j < 12; j++) {
        float t = (x[j] - mu) * inv * g[j] + b[j];
        y[j] = t > 0.f ? t : 0.f;
    }
}

// one 64-col block: QK -> bias+exp2 -> PV (ldmatrix.trans) + L
__device__ __forceinline__ void block64(
    int ch64, const uint4* Ks, uint32_t vlane,   // vlane = smem V base + lane*80
    const uint32_t aq[2][4], const uint32_t bh2[16],
    int lq, int le, float O[4][4], float L[4])
{
    const uint32_t ONES = 0x3C003C00u;
    float S[8][4];
    #pragma unroll
    for (int nt = 0; nt < 8; nt++) {
        uint4 w = Ks[(ch64 * 64 + nt * 8 + lq) * 4 + le];
        mma_f16_zc(S[nt], aq[0], w.x, w.y);
        mma_f16(S[nt], aq[1], w.z, w.w);
    }
    uint32_t P01[8], P23[8];
    #pragma unroll
    for (int nt = 0; nt < 8; nt++) {
        uint32_t a01 = pkf16(S[nt][0], S[nt][1]);
        uint32_t a23 = pkf16(S[nt][2], S[nt][3]);
        a01 = hadd2(a01, bh2[ch64 + nt + 1]);
        a23 = hadd2(a23, bh2[ch64 + nt]);
        P01[nt] = hex2(a01);
        P23[nt] = hex2(a23);
    }
    #pragma unroll
    for (int h = 0; h < 2; h++) {                 // kv halves of 32
        const int j0 = 2 * h, j1 = j0 + 1;        // 16-kv P blocks
        uint32_t ap0[4] = {P01[2*j0], P23[2*j0], P01[2*j0+1], P23[2*j0+1]};
        uint32_t ap1[4] = {P01[2*j1], P23[2*j1], P01[2*j1+1], P23[2*j1+1]};
        const uint32_t base = vlane + (uint32_t)(ch64 * 64 + 32 * h) * VROW_B;
        #pragma unroll
        for (int dt = 0; dt < 4; dt++) {
            uint32_t b0, b1, b2, b3;
            LDSM4T(b0, b1, b2, b3, base + dt * 16);
            mma_f16(O[dt], ap0, b0, b1);          // kv +0..15
            mma_f16(O[dt], ap1, b2, b3);          // kv +16..31
        }
        mma_f16(L, ap0, ONES, ONES);
        mma_f16(L, ap1, ONES, ONES);
    }
}

// ---------------------------------------------------------------------------
// Fused kernel: coalesced K+V f16 images (no transpose pass), 2 q-tiles
// ---------------------------------------------------------------------------
__global__ __launch_bounds__(256, 2) void attn_kernel(
    const float* __restrict__ q, const float* __restrict__ k,
    const float* __restrict__ v, float* __restrict__ out,
    const float* __restrict__ pw,  const float* __restrict__ pb,
    const float* __restrict__ g1,  const float* __restrict__ b1,
    const float* __restrict__ w1,  const float* __restrict__ bb1,
    const float* __restrict__ g2,  const float* __restrict__ b2,
    const float* __restrict__ w2,  const float* __restrict__ bb2,
    const float* __restrict__ g3,  const float* __restrict__ b3,
    const float* __restrict__ w3,  const float* __restrict__ bb3)
{
    extern __shared__ unsigned char smem[];
    uint32_t sbu;
    asm("{ .reg .u64 t; cvta.to.shared.u64 t, %1; cvt.u32.u64 %0, t; }" : "=r"(sbu) : "l"(smem));
    float* wts    = (float*)(smem + WT_OFF);
    float* biasSm = (float*)(smem + SB_OFF);

    const int qt2 = blockIdx.x, head = blockIdx.y, batch = blockIdx.z;
    const int bh = batch * H_ + head;
    const size_t bhOff = (size_t)bh * N_ * D_;
    const float* qb = q + bhOff;
    const float* kb = k + bhOff;
    const float* vb = v + bhOff;
    const int tid = threadIdx.x;
    const int warp = tid >> 5, lane = tid & 31;
    const int lq = lane >> 2, le = lane & 3, e0 = le * 2;
    const float scale = 0.17677669529663687f * LOG2E;

    // ---- weights -> smem ----
    if (tid < 36)  wts[tid] = pw[tid];
    if (tid < 12) {
        wts[36+tid]=pb[tid];  wts[48+tid]=g1[tid]; wts[60+tid]=b1[tid]; wts[216+tid]=bb1[tid];
        wts[228+tid]=g2[tid]; wts[240+tid]=b2[tid]; wts[396+tid]=bb2[tid];
        wts[408+tid]=g3[tid]; wts[420+tid]=b3[tid];
    }
    if (tid < 144) { wts[72+tid]=w1[tid]; wts[252+tid]=w2[tid]; }
    if (tid >= 144 && tid < 216) wts[432+tid-144] = w3[tid-144];
    if (tid >= 216 && tid < 222) wts[504+tid-216] = bb3[tid-216];

    // ---- K convert: coalesced LDG fp32 -> fp16 fragment image ----
    {
        uint4* Kimg = (uint4*)(smem + SK_OFF);
        for (int i = tid; i < N_ * 4; i += 256) {
            int n = i >> 2, l = i & 3, c0 = l * 2;
            const float* row = kb + (size_t)n * D_;
            float2 f0 = *(const float2*)(row + c0);
            float2 f1 = *(const float2*)(row + c0 + 8);
            float2 f2 = *(const float2*)(row + c0 + 16);
            float2 f3 = *(const float2*)(row + c0 + 24);
            uint4 w;
            w.x = pkf16(f0.x, f0.y); w.y = pkf16(f1.x, f1.y);
            w.z = pkf16(f2.x, f2.y); w.w = pkf16(f3.x, f3.y);
            Kimg[i] = w;
        }
    }

    // ---- V convert: coalesced LDG fp32 -> f16 row-major image [kv][32] ----
    {
        const float4* V4 = (const float4*)vb;      // [kv][8]
        for (int i = tid; i < N_ * 4; i += 256) {
            int kv = i >> 2, dg = i & 3;           // 8 floats per item
            float4 a = V4[kv * 8 + dg * 2];
            float4 b = V4[kv * 8 + dg * 2 + 1];
            uint4 o;
            o.x = pkf16(a.x, a.y); o.y = pkf16(a.z, a.w);
            o.z = pkf16(b.x, b.y); o.w = pkf16(b.z, b.w);
            *(uint4*)(smem + SV_OFF + kv * VROW_B + dg * 16) = o;
        }
    }

    // ---- tile-0 Q fragments (LDG; overlaps syncs) ----
    const int r0a = qt2 * 256 + warp * 16 + lq;
    const int r1a = r0a + 8;
    uint32_t aqA[2][4];
    #pragma unroll
    for (int ks = 0; ks < 2; ks++) {
        int cb = ks * 16 + e0;
        aqA[ks][0] = pkf16(qb[(size_t)r0a * D_ + cb] * scale,     qb[(size_t)r0a * D_ + cb + 1] * scale);
        aqA[ks][1] = pkf16(qb[(size_t)r1a * D_ + cb] * scale,     qb[(size_t)r1a * D_ + cb + 1] * scale);
        aqA[ks][2] = pkf16(qb[(size_t)r0a * D_ + cb + 8] * scale, qb[(size_t)r0a * D_ + cb + 9] * scale);
        aqA[ks][3] = pkf16(qb[(size_t)r1a * D_ + cb + 8] * scale, qb[(size_t)r1a * D_ + cb + 9] * scale);
    }

    __syncthreads();   // wts visible (K/V images complete)

    // ---- MLP: this head's 43 bias values ----
    if (tid < NIDX) {
        float c0 = -7.0f, c1 = (float)(tid / 15) - 7.0f, c2 = (float)(tid % 15) - 7.0f;
        float x[12], y[12];
        #pragma unroll
        for (int j = 0; j < 12; j++)
            x[j] = c0 * wts[j] + c1 * wts[12 + j] + c2 * wts[24 + j] + wts[36 + j];
        ln_relu12(x, wts+48, wts+60, y);
        #pragma unroll
        for (int j = 0; j < 12; j++) {
            float s = wts[216 + j];
            #pragma unroll
            for (int i = 0; i < 12; i++) s += y[i] * wts[72 + i * 12 + j];
            x[j] = s;
        }
        ln_relu12(x, wts+228, wts+240, y);
        #pragma unroll
        for (int j = 0; j < 12; j++) {
            float s = wts[396 + j];
            #pragma unroll
            for (int i = 0; i < 12; i++) s += y[i] * wts[252 + i * 12 + j];
            x[j] = s;
        }
        ln_relu12(x, wts+408, wts+420, y);
        float s = wts[504 + head];
        #pragma unroll
        for (int i = 0; i < 12; i++) s += y[i] * wts[432 + i * H_ + head];
        biasSm[tid] = s * LOG2E;
    }
    __syncthreads();   // biasSm visible

    const uint4* Ks = (const uint4*)(smem + SK_OFF);
    const uint32_t vlane = sbu + SV_OFF + (uint32_t)lane * VROW_B;
    float* ob = out + bhOff;

    // ---- two 128-row q tiles ----
    for (int mt = 0; mt < 2; mt++) {
        const int r0 = r0a + mt * 128;
        const int r1 = r0 + 8;
        const int sq0 = (r0 >> 6) + ((r0 >> 3) & 7) + (r0 & 7);

        uint32_t aq[2][4];
        if (mt == 0) {
            #pragma unroll
            for (int ks = 0; ks < 2; ks++)
                #pragma unroll
                for (int j = 0; j < 4; j++) aq[ks][j] = aqA[ks][j];
        } else {
            #pragma unroll
            for (int ks = 0; ks < 2; ks++) {
                int cb = ks * 16 + e0;
                aq[ks][0] = pkf16(qb[(size_t)r0 * D_ + cb] * scale,     qb[(size_t)r0 * D_ + cb + 1] * scale);
                aq[ks][1] = pkf16(qb[(size_t)r1 * D_ + cb] * scale,     qb[(size_t)r1 * D_ + cb + 1] * scale);
                aq[ks][2] = pkf16(qb[(size_t)r0 * D_ + cb + 8] * scale, qb[(size_t)r0 * D_ + cb + 9] * scale);
                aq[ks][3] = pkf16(qb[(size_t)r1 * D_ + cb + 8] * scale, qb[(size_t)r1 * D_ + cb + 9] * scale);
            }
        }

        const int A1 = sq0 + 22 - e0;
        uint32_t bh2[16];
        {
            float br[17];
            #pragma unroll
            for (int u = 0; u < 17; u++) br[u] = biasSm[A1 - u];
            #pragma unroll
            for (int u = 0; u < 16; u++) bh2[u] = pkf16(br[u], br[u + 1]);
        }

        float O[4][4];
        #pragma unroll
        for (int d = 0; d < 4; d++)
            #pragma unroll
            for (int j = 0; j < 4; j++) O[d][j] = 0.f;
        float L[4] = {0.f, 0.f, 0.f, 0.f};

        #pragma unroll
        for (int ch64 = 0; ch64 < 8; ch64++)
            block64(ch64, Ks, vlane, aq, bh2, lq, le, O, L);

        float i0 = 1.f / L[0], i1 = 1.f / L[2];
        #pragma unroll
        for (int dt = 0; dt < 4; dt++) {
            int c = dt * 8 + e0;
            float2 o01; o01.x = O[dt][0] * i0; o01.y = O[dt][1] * i0;
            float2 o23; o23.x = O[dt][2] * i1; o23.y = O[dt][3] * i1;
            *(float2*)(ob + (size_t)r0 * D_ + c) = o01;
            *(float2*)(ob + (size_t)r1 * D_ + c) = o23;
        }
    }
}

// ---------------------------------------------------------------------------
extern "C" void kernel_launch(void* const* d_in, const int* in_sizes, int n_in,
                              void* d_out, int out_size)
{
    const float* q = (const float*)d_in[0];
    const float* k = (const float*)d_in[1];
    const float* v = (const float*)d_in[2];
    int base = (in_sizes[3] == 36) ? 3 : 6;
    const float* pw  = (const float*)d_in[base + 0];
    const float* pb  = (const float*)d_in[base + 1];
    const float* g1  = (const float*)d_in[base + 2];
    const float* b1  = (const float*)d_in[base + 3];
    const float* w1  = (const float*)d_in[base + 4];
    const float* bb1 = (const float*)d_in[base + 5];
    const float* g2  = (const float*)d_in[base + 6];
    const float* b2  = (const float*)d_in[base + 7];
    const float* w2  = (const float*)d_in[base + 8];
    const float* bb2 = (const float*)d_in[base + 9];
    const float* g3  = (const float*)d_in[base + 10];
    const float* b3  = (const float*)d_in[base + 11];
    const float* w3  = (const float*)d_in[base + 12];
    const float* bb3 = (const float*)d_in[base + 13];
    float* out = (float*)d_out;

    cudaFuncSetAttribute(attn_kernel, cudaFuncAttributeMaxDynamicSharedMemorySize, SMEM_SZ);

    dim3 grid(2, H_, B_);
    attn_kernel<<<grid, 256, SMEM_SZ>>>(q, k, v, out, pw, pb, g1, b1, w1, bb1,
                                        g2, b2, w2, bb2, g3, b3, w3, bb3);
}

// round 17
// speedup vs baseline: 1.0174x; 1.0174x over previous
#include <cuda_runtime.h>
#include <cuda_fp16.h>
#include <stdint.h>

#define B_    64
#define H_    6
#define N_    512
#define D_    32
#define NIDX  43
#define LOG2E 1.4426950408889634f

// smem: K image 32KB | V image 32 x 68 u4 | scratch A,B 128x36 f32 | wts | bias
#define SK_OFF   0
#define SV_OFF   32768
#define VROW_U   68
#define VSTA_OFF (SV_OFF + D_*VROW_U*16)    // 67584
#define VSTB_OFF (VSTA_OFF + 128*36*4)      // 86016
#define WT_OFF   (VSTB_OFF + 128*36*4)      // 104448
#define SB_OFF   (WT_OFF + 2048)            // 106496
#define SMEM_SZ  (SB_OFF + 192)             // 106688 -> 2 CTAs/SM

// ---------------- helpers ----------------
__device__ __forceinline__ uint32_t pkf16(float x0, float x1) {
    uint32_t r; asm("cvt.rn.f16x2.f32 %0, %1, %2;" : "=r"(r) : "f"(x1), "f"(x0)); return r;
}
__device__ __forceinline__ uint32_t hadd2(uint32_t a, uint32_t b) {
    uint32_t r; asm("add.rn.f16x2 %0, %1, %2;" : "=r"(r) : "r"(a), "r"(b)); return r;
}
__device__ __forceinline__ uint32_t hex2(uint32_t a) {
    uint32_t r; asm("ex2.approx.f16x2 %0, %1;" : "=r"(r) : "r"(a)); return r;
}
__device__ __forceinline__ void mma_f16(float c[4], const uint32_t a[4], uint32_t b0, uint32_t b1) {
    asm volatile(
        "mma.sync.aligned.m16n8k16.row.col.f32.f16.f16.f32 "
        "{%0,%1,%2,%3}, {%4,%5,%6,%7}, {%8,%9}, {%0,%1,%2,%3};\n"
        : "+f"(c[0]), "+f"(c[1]), "+f"(c[2]), "+f"(c[3])
        : "r"(a[0]), "r"(a[1]), "r"(a[2]), "r"(a[3]), "r"(b0), "r"(b1));
}
__device__ __forceinline__ void mma_f16_zc(float d[4], const uint32_t a[4], uint32_t b0, uint32_t b1) {
    asm volatile(
        "mma.sync.aligned.m16n8k16.row.col.f32.f16.f16.f32 "
        "{%0,%1,%2,%3}, {%4,%5,%6,%7}, {%8,%9}, {%10,%11,%12,%13};\n"
        : "=f"(d[0]), "=f"(d[1]), "=f"(d[2]), "=f"(d[3])
        : "r"(a[0]), "r"(a[1]), "r"(a[2]), "r"(a[3]), "r"(b0), "r"(b1),
          "f"(0.f), "f"(0.f), "f"(0.f), "f"(0.f));
}
__device__ __forceinline__ void cp16(uint32_t dst, const void* src) {
    asm volatile("cp.async.cg.shared.global [%0], [%1], 16;" :: "r"(dst), "l"(src));
}
#define CP_COMMIT() asm volatile("cp.async.commit_group;" ::: "memory")
#define CP_WAIT(n)  asm volatile("cp.async.wait_group %0;" :: "n"(n) : "memory")
#define BAR_GRP()   asm volatile("bar.sync 1, 192;" ::: "memory")

__device__ __forceinline__ void ln_relu12(const float* x, const float* g, const float* b, float* y) {
    float mu = 0.f;
    #pragma unroll
    for (int j = 0; j < 12; j++) mu += x[j];
    mu *= (1.f / 12.f);
    float var = 0.f;
    #pragma unroll
    for (int j = 0; j < 12; j++) { float d = x[j] - mu; var += d * d; }
    var *= (1.f / 12.f);
    float inv = rsqrtf(var + 1e-5f);
    #pragma unroll
    for (int j = 0; j < 12; j++) {
        float t = (x[j] - mu) * inv * g[j] + b[j];
        y[j] = t > 0.f ? t : 0.f;
    }
}

// one 64-col block: QK -> bias+exp2 -> PV + L   (identical to R15)
__device__ __forceinline__ void block64(
    int ch64, const uint4* Ks, const uint4* Vs,
    const uint32_t aq[2][4], const uint32_t bh2[16],
    int lq, int le, float O[4][4], float L[4])
{
    const uint32_t ONES = 0x3C003C00u;
    float S[8][4];
    #pragma unroll
    for (int nt = 0; nt < 8; nt++) {
        uint4 w = Ks[(ch64 * 64 + nt * 8 + lq) * 4 + le];
        mma_f16_zc(S[nt], aq[0], w.x, w.y);
        mma_f16(S[nt], aq[1], w.z, w.w);
    }
    uint32_t P01[8], P23[8];
    #pragma unroll
    for (int nt = 0; nt < 8; nt++) {
        uint32_t a01 = pkf16(S[nt][0], S[nt][1]);
        uint32_t a23 = pkf16(S[nt][2], S[nt][3]);
        a01 = hadd2(a01, bh2[ch64 + nt + 1]);
        a23 = hadd2(a23, bh2[ch64 + nt]);
        P01[nt] = hex2(a01);
        P23[nt] = hex2(a23);
    }
    #pragma unroll
    for (int kp2 = 0; kp2 < 2; kp2++) {
        const int j0 = kp2 * 2, j1 = j0 + 1;
        uint32_t ap0[4] = {P01[2*j0], P23[2*j0], P01[2*j0+1], P23[2*j0+1]};
        uint32_t ap1[4] = {P01[2*j1], P23[2*j1], P01[2*j1+1], P23[2*j1+1]};
        const int wb = (ch64 * 2 + kp2) * 4 + le;
        #pragma unroll
        for (int dt = 0; dt < 4; dt++) {
            uint4 w = Vs[(dt * 8 + lq) * VROW_U + wb];
            mma_f16(O[dt], ap0, w.x, w.y);
            mma_f16(O[dt], ap1, w.z, w.w);
        }
        mma_f16(L, ap0, ONES, ONES);
        mma_f16(L, ap1, ONES, ONES);
    }
}

// pack one 128-kv chunk (scratch -> fragment image), w base = 16*c
__device__ __forceinline__ void pack128(
    const float4* vs4, uint4* Vimg, int c, int t0, int nthr)
{
    for (int it = t0; it < 128; it += nthr) {
        int dq = it >> 4, wl = it & 15;          // dq 0..7, wl = kp*4+le (local)
        int kp = wl >> 2, l = wl & 3;
        int k0 = 32 * kp + 2 * l;                // local kv
        int w = 16 * c + wl;                     // global w
        float4 fa0 = vs4[(k0 +  0) * 9 + dq], fa1 = vs4[(k0 +  1) * 9 + dq];
        float4 fb0 = vs4[(k0 +  8) * 9 + dq], fb1 = vs4[(k0 +  9) * 9 + dq];
        float4 fc0 = vs4[(k0 + 16) * 9 + dq], fc1 = vs4[(k0 + 17) * 9 + dq];
        float4 fd0 = vs4[(k0 + 24) * 9 + dq], fd1 = vs4[(k0 + 25) * 9 + dq];
        uint4 o;
        o.x = pkf16(fa0.x, fa1.x); o.y = pkf16(fb0.x, fb1.x);
        o.z = pkf16(fc0.x, fc1.x); o.w = pkf16(fd0.x, fd1.x);
        Vimg[(4 * dq + 0) * VROW_U + w] = o;
        o.x = pkf16(fa0.y, fa1.y); o.y = pkf16(fb0.y, fb1.y);
        o.z = pkf16(fc0.y, fc1.y); o.w = pkf16(fd0.y, fd1.y);
        Vimg[(4 * dq + 1) * VROW_U + w] = o;
        o.x = pkf16(fa0.z, fa1.z); o.y = pkf16(fb0.z, fb1.z);
        o.z = pkf16(fc0.z, fc1.z); o.w = pkf16(fd0.z, fd1.z);
        Vimg[(4 * dq + 2) * VROW_U + w] = o;
        o.x = pkf16(fa0.w, fa1.w); o.y = pkf16(fb0.w, fb1.w);
        o.z = pkf16(fc0.w, fc1.w); o.w = pkf16(fd0.w, fd1.w);
        Vimg[(4 * dq + 3) * VROW_U + w] = o;
    }
}

// ---------------------------------------------------------------------------
// Fused kernel: double-buffered V pipeline + warp-specialized MLP, 2 q-tiles
// ---------------------------------------------------------------------------
__global__ __launch_bounds__(256, 2) void attn_kernel(
    const float* __restrict__ q, const float* __restrict__ k,
    const float* __restrict__ v, float* __restrict__ out,
    const float* __restrict__ pw,  const float* __restrict__ pb,
    const float* __restrict__ g1,  const float* __restrict__ b1,
    const float* __restrict__ w1,  const float* __restrict__ bb1,
    const float* __restrict__ g2,  const float* __restrict__ b2,
    const float* __restrict__ w2,  const float* __restrict__ bb2,
    const float* __restrict__ g3,  const float* __restrict__ b3,
    const float* __restrict__ w3,  const float* __restrict__ bb3)
{
    extern __shared__ unsigned char smem[];
    uint32_t sbu;
    asm("{ .reg .u64 t; cvta.to.shared.u64 t, %1; cvt.u32.u64 %0, t; }" : "=r"(sbu) : "l"(smem));
    float* wts    = (float*)(smem + WT_OFF);
    float* biasSm = (float*)(smem + SB_OFF);
    const float4* vsA = (const float4*)(smem + VSTA_OFF);
    const float4* vsB = (const float4*)(smem + VSTB_OFF);
    uint4* Vimg = (uint4*)(smem + SV_OFF);

    const int qt2 = blockIdx.x, head = blockIdx.y, batch = blockIdx.z;
    const int bh = batch * H_ + head;
    const size_t bhOff = (size_t)bh * N_ * D_;
    const float* qb = q + bhOff;
    const float* kb = k + bhOff;
    const float* vb = v + bhOff;
    const int tid = threadIdx.x;
    const int warp = tid >> 5, lane = tid & 31;
    const int lq = lane >> 2, le = lane & 3, e0 = le * 2;
    const float scale = 0.17677669529663687f * LOG2E;

    // ---- warps 2-7: issue V chunks 0 and 1 up front (separate groups) ----
    if (tid >= 64) {
        const int t0 = tid - 64;
        for (int i = t0; i < 128 * 8; i += 192) {
            int kv = i >> 3, dch = i & 7;
            cp16(sbu + VSTA_OFF + (kv * 36 + dch * 4) * 4, vb + kv * 32 + dch * 4);
        }
        CP_COMMIT();
        for (int i = t0; i < 128 * 8; i += 192) {
            int kv = i >> 3, dch = i & 7;
            cp16(sbu + VSTB_OFF + (kv * 36 + dch * 4) * 4, vb + (128 + kv) * 32 + dch * 4);
        }
        CP_COMMIT();
    }

    // ---- all: weights -> smem ----
    if (tid < 36)  wts[tid] = pw[tid];
    if (tid < 12) {
        wts[36+tid]=pb[tid];  wts[48+tid]=g1[tid]; wts[60+tid]=b1[tid]; wts[216+tid]=bb1[tid];
        wts[228+tid]=g2[tid]; wts[240+tid]=b2[tid]; wts[396+tid]=bb2[tid];
        wts[408+tid]=g3[tid]; wts[420+tid]=b3[tid];
    }
    if (tid < 144) { wts[72+tid]=w1[tid]; wts[252+tid]=w2[tid]; }
    if (tid >= 144 && tid < 216) wts[432+tid-144] = w3[tid-144];
    if (tid >= 216 && tid < 222) wts[504+tid-216] = bb3[tid-216];

    // ---- all: K convert (coalesced) ----
    {
        uint4* Kimg = (uint4*)(smem + SK_OFF);
        for (int i = tid; i < N_ * 4; i += 256) {
            int n = i >> 2, l = i & 3, c0 = l * 2;
            const float* row = kb + (size_t)n * D_;
            float2 f0 = *(const float2*)(row + c0);
            float2 f1 = *(const float2*)(row + c0 + 8);
            float2 f2 = *(const float2*)(row + c0 + 16);
            float2 f3 = *(const float2*)(row + c0 + 24);
            uint4 w;
            w.x = pkf16(f0.x, f0.y); w.y = pkf16(f1.x, f1.y);
            w.z = pkf16(f2.x, f2.y); w.w = pkf16(f3.x, f3.y);
            Kimg[i] = w;
        }
    }

    // ---- tile-0 Q fragments ----
    const int r0a = qt2 * 256 + warp * 16 + lq;
    const int r1a = r0a + 8;
    uint32_t aqA[2][4];
    #pragma unroll
    for (int ks = 0; ks < 2; ks++) {
        int cb = ks * 16 + e0;
        aqA[ks][0] = pkf16(qb[(size_t)r0a * D_ + cb] * scale,     qb[(size_t)r0a * D_ + cb + 1] * scale);
        aqA[ks][1] = pkf16(qb[(size_t)r1a * D_ + cb] * scale,     qb[(size_t)r1a * D_ + cb + 1] * scale);
        aqA[ks][2] = pkf16(qb[(size_t)r0a * D_ + cb + 8] * scale, qb[(size_t)r0a * D_ + cb + 9] * scale);
        aqA[ks][3] = pkf16(qb[(size_t)r1a * D_ + cb + 8] * scale, qb[(size_t)r1a * D_ + cb + 9] * scale);
    }

    __syncthreads();   // wts visible (K image complete)

    if (tid < 64) {
        // ---- warps 0-1: MLP while warps 2-7 run the V pipeline ----
        if (tid < NIDX) {
            float c0 = -7.0f, c1 = (float)(tid / 15) - 7.0f, c2 = (float)(tid % 15) - 7.0f;
            float x[12], y[12];
            #pragma unroll
            for (int j = 0; j < 12; j++)
                x[j] = c0 * wts[j] + c1 * wts[12 + j] + c2 * wts[24 + j] + wts[36 + j];
            ln_relu12(x, wts+48, wts+60, y);
            #pragma unroll
            for (int j = 0; j < 12; j++) {
                float s = wts[216 + j];
                #pragma unroll
                for (int i = 0; i < 12; i++) s += y[i] * wts[72 + i * 12 + j];
                x[j] = s;
            }
            ln_relu12(x, wts+228, wts+240, y);
            #pragma unroll
            for (int j = 0; j < 12; j++) {
                float s = wts[396 + j];
                #pragma unroll
                for (int i = 0; i < 12; i++) s += y[i] * wts[252 + i * 12 + j];
                x[j] = s;
            }
            ln_relu12(x, wts+408, wts+420, y);
            float s = wts[504 + head];
            #pragma unroll
            for (int i = 0; i < 12; i++) s += y[i] * wts[432 + i * H_ + head];
            biasSm[tid] = s * LOG2E;
        }
    } else {
        // ---- warps 2-7: double-buffered wait/pack/issue pipeline ----
        const int t0 = tid - 64;
        CP_WAIT(1);  BAR_GRP();                 // c0 landed in A
        pack128(vsA, Vimg, 0, t0, 192);
        BAR_GRP();                              // A reads done
        for (int i = t0; i < 128 * 8; i += 192) {   // c2 -> A
            int kv = i >> 3, dch = i & 7;
            cp16(sbu + VSTA_OFF + (kv * 36 + dch * 4) * 4, vb + (256 + kv) * 32 + dch * 4);
        }
        CP_COMMIT();
        CP_WAIT(1);  BAR_GRP();                 // c1 landed in B
        pack128(vsB, Vimg, 1, t0, 192);
        BAR_GRP();                              // B reads done
        for (int i = t0; i < 128 * 8; i += 192) {   // c3 -> B
            int kv = i >> 3, dch = i & 7;
            cp16(sbu + VSTB_OFF + (kv * 36 + dch * 4) * 4, vb + (384 + kv) * 32 + dch * 4);
        }
        CP_COMMIT();
        CP_WAIT(1);  BAR_GRP();                 // c2 landed in A
        pack128(vsA, Vimg, 2, t0, 192);
        CP_WAIT(0);  BAR_GRP();                 // c3 landed in B
        pack128(vsB, Vimg, 3, t0, 192);
    }
    __syncthreads();   // V image + biasSm visible to all

    const uint4* Ks = (const uint4*)(smem + SK_OFF);
    const uint4* Vs = (const uint4*)(smem + SV_OFF);
    float* ob = out + bhOff;

    // ---- two 128-row q tiles ----
    for (int mt = 0; mt < 2; mt++) {
        const int r0 = r0a + mt * 128;
        const int r1 = r0 + 8;
        const int sq0 = (r0 >> 6) + ((r0 >> 3) & 7) + (r0 & 7);

        uint32_t aq[2][4];
        if (mt == 0) {
            #pragma unroll
            for (int ks = 0; ks < 2; ks++)
                #pragma unroll
                for (int j = 0; j < 4; j++) aq[ks][j] = aqA[ks][j];
        } else {
            #pragma unroll
            for (int ks = 0; ks < 2; ks++) {
                int cb = ks * 16 + e0;
                aq[ks][0] = pkf16(qb[(size_t)r0 * D_ + cb] * scale,     qb[(size_t)r0 * D_ + cb + 1] * scale);
                aq[ks][1] = pkf16(qb[(size_t)r1 * D_ + cb] * scale,     qb[(size_t)r1 * D_ + cb + 1] * scale);
                aq[ks][2] = pkf16(qb[(size_t)r0 * D_ + cb + 8] * scale, qb[(size_t)r0 * D_ + cb + 9] * scale);
                aq[ks][3] = pkf16(qb[(size_t)r1 * D_ + cb + 8] * scale, qb[(size_t)r1 * D_ + cb + 9] * scale);
            }
        }

        const int A1 = sq0 + 22 - e0;
        uint32_t bh2[16];
        {
            float br[17];
            #pragma unroll
            for (int u = 0; u < 17; u++) br[u] = biasSm[A1 - u];
            #pragma unroll
            for (int u = 0; u < 16; u++) bh2[u] = pkf16(br[u], br[u + 1]);
        }

        float O[4][4];
        #pragma unroll
        for (int d = 0; d < 4; d++)
            #pragma unroll
            for (int j = 0; j < 4; j++) O[d][j] = 0.f;
        float L[4] = {0.f, 0.f, 0.f, 0.f};

        #pragma unroll
        for (int ch64 = 0; ch64 < 8; ch64++)
            block64(ch64, Ks, Vs, aq, bh2, lq, le, O, L);

        float i0 = 1.f / L[0], i1 = 1.f / L[2];
        #pragma unroll
        for (int dt = 0; dt < 4; dt++) {
            int c = dt * 8 + e0;
            float2 o01; o01.x = O[dt][0] * i0; o01.y = O[dt][1] * i0;
            float2 o23; o23.x = O[dt][2] * i1; o23.y = O[dt][3] * i1;
            *(float2*)(ob + (size_t)r0 * D_ + c) = o01;
            *(float2*)(ob + (size_t)r1 * D_ + c) = o23;
        }
    }
}

// ---------------------------------------------------------------------------
extern "C" void kernel_launch(void* const* d_in, const int* in_sizes, int n_in,
                              void* d_out, int out_size)
{
    const float* q = (const float*)d_in[0];
    const float* k = (const float*)d_in[1];
    const float* v = (const float*)d_in[2];
    int base = (in_sizes[3] == 36) ? 3 : 6;
    const float* pw  = (const float*)d_in[base + 0];
    const float* pb  = (const float*)d_in[base + 1];
    const float* g1  = (const float*)d_in[base + 2];
    const float* b1  = (const float*)d_in[base + 3];
    const float* w1  = (const float*)d_in[base + 4];
    const float* bb1 = (const float*)d_in[base + 5];
    const float* g2  = (const float*)d_in[base + 6];
    const float* b2  = (const float*)d_in[base + 7];
    const float* w2  = (const float*)d_in[base + 8];
    const float* bb2 = (const float*)d_in[base + 9];
    const float* g3  = (const float*)d_in[base + 10];
    const float* b3  = (const float*)d_in[base + 11];
    const float* w3  = (const float*)d_in[base + 12];
    const float* bb3 = (const float*)d_in[base + 13];
    float* out = (float*)d_out;

    cudaFuncSetAttribute(attn_kernel, cudaFuncAttributeMaxDynamicSharedMemorySize, SMEM_SZ);

    dim3 grid(2, H_, B_);
    attn_kernel<<<grid, 256, SMEM_SZ>>>(q, k, v, out, pw, pb, g1, b1, w1, bb1,
                                        g2, b2, w2, bb2, g3, b3, w3, bb3);
}